// round 9
// baseline (speedup 1.0000x reference)
#include <cuda_runtime.h>
#include <cuda_fp16.h>
#include <cstdint>

// ============================================================================
// QuantLinear: out[M,N] = x[M,K] @ dequant(qweight, scales, qzeros)[K,N]
// M=8192, K=4096, N=11008, groupsize=128, 4-bit.
//
// compute_103 => mma.sync HMMA, rt_SMSP=8; GEMM floor 1.21ms. Proven config:
// CTA 128x128x64, 256 thr, 8 warps 64x32, 3-stage cp.async, 2 CTAs/SM,
// fill issued after compute (R8: 1.505ms GEMM, tensor 81%).
//
// R9 changes (register-neutral scheduling only):
//  - wait_group moved before compute (stage i+1 resident during compute i)
//  - B-fragment double buffer across ks AND across the stage boundary
//  - A fragments loaded in halves of 2 (peak fragment regs flat)
// ============================================================================

constexpr int M = 8192;
constexpr int N = 11008;
constexpr int K = 4096;

constexpr int BM = 128;
constexpr int BN = 128;
constexpr int KC = 64;             // halves per stage = 128B rows (SW128)
constexpr int STAGES = 3;
constexpr int NK = K / KC;         // 64
constexpr int THREADS = 256;

constexpr int A_BYTES = BM * 128;                 // 16384
constexpr int STAGE_BYTES = 2 * A_BYTES;          // 32768 (A then B)
constexpr int SMEM_BYTES = STAGES * STAGE_BYTES;  // 98304 -> 2 CTAs/SM

constexpr int XWORK = M * K / 4;        // float4 items in convert part
constexpr int WWORK = (K / 8) * N;      // int32 items in dequant part

static_assert(M % BM == 0 && N % BN == 0 && K % KC == 0, "exact tiling");

__device__ __half g_X[(size_t)M * K];   // [M, K] fp16
__device__ __half g_W[(size_t)N * K];   // [N, K] fp16 (W^T), K-major

// ----------------------------------------------------------------------------
// helpers
// ----------------------------------------------------------------------------
__device__ __forceinline__ void cp16(uint32_t smem_dst, const void* gsrc) {
    asm volatile("cp.async.cg.shared.global [%0], [%1], 16;"
                 :: "r"(smem_dst), "l"(gsrc));
}

__device__ __forceinline__ void ldsm4(uint32_t* r, uint32_t addr) {
    asm volatile("ldmatrix.sync.aligned.m8n8.x4.shared.b16 {%0,%1,%2,%3}, [%4];"
                 : "=r"(r[0]), "=r"(r[1]), "=r"(r[2]), "=r"(r[3]) : "r"(addr));
}

__device__ __forceinline__ void mma16816(float* c, const uint32_t* a, const uint32_t* b) {
    asm volatile(
        "mma.sync.aligned.m16n8k16.row.col.f32.f16.f16.f32 "
        "{%0,%1,%2,%3}, {%4,%5,%6,%7}, {%8,%9}, {%0,%1,%2,%3};"
        : "+f"(c[0]), "+f"(c[1]), "+f"(c[2]), "+f"(c[3])
        : "r"(a[0]), "r"(a[1]), "r"(a[2]), "r"(a[3]), "r"(b[0]), "r"(b[1]));
}

// ----------------------------------------------------------------------------
// Pass 1: fused x-convert + dequant (validated R4..R8)
// ----------------------------------------------------------------------------
__global__ void __launch_bounds__(256)
prep_kernel(const float* __restrict__ x, const int* __restrict__ qweight,
            const float* __restrict__ scales, const int* __restrict__ qzeros) {
    int idx = blockIdx.x * 256 + threadIdx.x;
    if (idx < XWORK) {
        float4 v = ((const float4*)x)[idx];
        __half2 h0 = __floats2half2_rn(v.x, v.y);
        __half2 h1 = __floats2half2_rn(v.z, v.w);
        uint2 o;
        o.x = *(unsigned*)&h0;
        o.y = *(unsigned*)&h1;
        ((uint2*)g_X)[idx] = o;
        return;
    }
    int widx = idx - XWORK;          // over (K/8)*N
    if (widx >= WWORK) return;
    int n = widx % N;
    int r = widx / N;
    int g = r >> 4;                  // groupsize 128 = 16 qweight rows
    unsigned q  = ((const unsigned*)qweight)[widx];
    unsigned qz = ((const unsigned*)qzeros)[g * (N / 8) + (n >> 3)];
    float z = (float)((qz >> ((n & 7) * 4)) & 0xF);
    float s = scales[g * N + n];
    __half2 outv[4];
#pragma unroll
    for (int j = 0; j < 4; j++) {
        float v0 = s * ((float)((q >> (8 * j))     & 0xF) - z);
        float v1 = s * ((float)((q >> (8 * j + 4)) & 0xF) - z);
        outv[j] = __floats2half2_rn(v0, v1);
    }
    *(uint4*)&g_W[(size_t)n * K + r * 8] = *(uint4*)outv;
}

// ----------------------------------------------------------------------------
// Stage loader: A 128 rows + B 128 rows, 128B/row, SW128.
// ----------------------------------------------------------------------------
__device__ __forceinline__ void load_stage(uint32_t sbase, int slot, int kt,
                                           const __half* Ag, const __half* Bg,
                                           int tid) {
    const uint32_t a_s = sbase + slot * STAGE_BYTES;
    const uint32_t b_s = a_s + A_BYTES;
    const __half* Ak = Ag + kt * KC;
    const __half* Bk = Bg + kt * KC;
#pragma unroll
    for (int it = 0; it < 4; it++) {        // 128 rows * 8 chunks / 256 thr
        int idx = tid + it * THREADS;
        int r = idx >> 3, c = idx & 7;
        uint32_t off = (uint32_t)r * 128 + (uint32_t)((c ^ (r & 7)) * 16);
        cp16(a_s + off, Ak + (size_t)r * K + c * 8);
        cp16(b_s + off, Bk + (size_t)r * K + c * 8);
    }
}

// ----------------------------------------------------------------------------
// Pass 2: GEMM
// ----------------------------------------------------------------------------
__global__ void __launch_bounds__(THREADS, 2)
gemm_kernel(float* __restrict__ out) {
    extern __shared__ char smem[];
    const uint32_t sbase = (uint32_t)__cvta_generic_to_shared(smem);
    const int tid  = threadIdx.x;
    const int warp = tid >> 5;
    const int lane = tid & 31;
    const int wm = warp & 1;          // 2 warps over 128 M (64 each)
    const int wn = warp >> 1;         // 4 warps over 128 N (32 each)
    const int m0 = blockIdx.x * BM;
    const int n0 = blockIdx.y * BN;

    const __half* Ag = g_X + (size_t)m0 * K;
    const __half* Bg = g_W + (size_t)n0 * K;

    float acc[4][4][4];
#pragma unroll
    for (int i = 0; i < 4; i++)
#pragma unroll
        for (int j = 0; j < 4; j++)
#pragma unroll
            for (int e = 0; e < 4; e++) acc[i][j][e] = 0.f;

    // ldmatrix address components (validated R2..R8):
    const int arow = wm * 64 + (lane & 15);
    const int asel = lane >> 4;                              // k-chunk +0/+1
    const int brow = wn * 32 + (((lane >> 4) & 1) << 3) + (lane & 7);
    const int bsel = (lane >> 3) & 1;

    // B fragments, double-buffered (carried across ks and stage boundaries)
    uint32_t bfr[2][2][4];

    auto ldb = [&](uint32_t b_s, int ks, int buf) {
        const int kc = ks * 2 + bsel;
#pragma unroll
        for (int nf2 = 0; nf2 < 2; nf2++) {
            int row = brow + nf2 * 16;
            ldsm4(bfr[buf][nf2], b_s + row * 128 + ((kc ^ (row & 7)) * 16));
        }
    };

    // prologue: fills for stages 0,1 in flight; stage 0 resident after sync
    load_stage(sbase, 0, 0, Ag, Bg, tid);
    asm volatile("cp.async.commit_group;" ::: "memory");
    load_stage(sbase, 1, 1, Ag, Bg, tid);
    asm volatile("cp.async.commit_group;" ::: "memory");
    asm volatile("cp.async.wait_group 1;" ::: "memory");
    __syncthreads();

    // preload ks=0 B fragments of stage 0 into buffer 0
    ldb(sbase + A_BYTES, 0, 0);

    int slot = 0;       // slot of stage i
    for (int i = 0; i < NK; i++) {
        const uint32_t a_s = sbase + slot * STAGE_BYTES;
        const int slot_n = (slot + 1 == STAGES) ? 0 : slot + 1;        // stage i+1
        const int slot_f = (slot_n + 1 == STAGES) ? 0 : slot_n + 1;    // stage i+2
        const uint32_t b_s      = a_s + A_BYTES;
        const uint32_t b_s_next = sbase + slot_n * STAGE_BYTES + A_BYTES;

        // fill stage i+2 into slot_f = slot(i-1): reads of that slot finished
        // before the barrier that ended iter i-1.
        if (i + 2 < NK)
            load_stage(sbase, slot_f, i + 2, Ag, Bg, tid);
        asm volatile("cp.async.commit_group;" ::: "memory");

        // stage i+1 guaranteed resident from here on
        asm volatile("cp.async.wait_group 1;" ::: "memory");

#pragma unroll
        for (int ks = 0; ks < KC / 16; ks++) {
            const int cur = ks & 1;
            uint32_t a01[2][4];
#pragma unroll
            for (int mf = 0; mf < 2; mf++) {          // A half 0 (mf 0,1)
                int row = arow + mf * 16;
                int kc  = ks * 2 + asel;
                ldsm4(a01[mf], a_s + row * 128 + ((kc ^ (row & 7)) * 16));
            }
            if (ks < KC / 16 - 1)                     // prefetch next B frags
                ldb(b_s, ks + 1, cur ^ 1);
            else if (i + 1 < NK)                      // ...or next stage ks=0
                ldb(b_s_next, 0, cur ^ 1);
#pragma unroll
            for (int mf = 0; mf < 2; mf++)
#pragma unroll
                for (int nf = 0; nf < 4; nf++)
                    mma16816(acc[mf][nf], a01[mf],
                             &bfr[cur][nf >> 1][(nf & 1) * 2]);
            uint32_t a23[2][4];
#pragma unroll
            for (int mf = 0; mf < 2; mf++) {          // A half 1 (mf 2,3)
                int row = arow + (mf + 2) * 16;
                int kc  = ks * 2 + asel;
                ldsm4(a23[mf], a_s + row * 128 + ((kc ^ (row & 7)) * 16));
            }
#pragma unroll
            for (int mf = 0; mf < 2; mf++)
#pragma unroll
                for (int nf = 0; nf < 4; nf++)
                    mma16816(acc[mf + 2][nf], a23[mf],
                             &bfr[cur][nf >> 1][(nf & 1) * 2]);
        }

        slot = slot_n;
        __syncthreads();   // all reads of slot(i) done before iter i+1 refills it
    }

    // Epilogue: register -> gmem float2 stores
    const int mbase = m0 + wm * 64 + (lane >> 2);
    const int nbase = n0 + wn * 32 + (lane & 3) * 2;
#pragma unroll
    for (int mf = 0; mf < 4; mf++)
#pragma unroll
        for (int nf = 0; nf < 4; nf++) {
            float* p0 = &out[(size_t)(mbase + mf * 16)     * N + nbase + nf * 8];
            float* p1 = &out[(size_t)(mbase + mf * 16 + 8) * N + nbase + nf * 8];
            *(float2*)p0 = make_float2(acc[mf][nf][0], acc[mf][nf][1]);
            *(float2*)p1 = make_float2(acc[mf][nf][2], acc[mf][nf][3]);
        }
}

// ----------------------------------------------------------------------------
extern "C" void kernel_launch(void* const* d_in, const int* in_sizes, int n_in,
                              void* d_out, int out_size) {
    (void)in_sizes; (void)n_in; (void)out_size;
    const float* x       = (const float*)d_in[0];
    const int*   qweight = (const int*)d_in[1];
    const float* scales  = (const float*)d_in[2];
    const int*   qzeros  = (const int*)d_in[3];
    float* out = (float*)d_out;

    prep_kernel<<<(XWORK + WWORK + 255) / 256, 256>>>(x, qweight, scales, qzeros);

    cudaFuncSetAttribute(gemm_kernel, cudaFuncAttributeMaxDynamicSharedMemorySize,
                         SMEM_BYTES);
    dim3 grid(M / BM, N / BN);   // (64, 86), m-fast: wave shares B via L2
    gemm_kernel<<<grid, THREADS, SMEM_BYTES>>>(out);
}

// round 10
// speedup vs baseline: 1.0406x; 1.0406x over previous
#include <cuda_runtime.h>
#include <cuda_fp16.h>
#include <cstdint>

// ============================================================================
// QuantLinear: out[M,N] = x[M,K] @ dequant(qweight, scales, qzeros)[K,N]
// M=8192, K=4096, N=11008, groupsize=128, 4-bit.
//
// compute_103 => mma.sync HMMA, rt_SMSP=8; GEMM floor 1.21ms.
// GEMM = R8 byte-identical (best measured: 1.505ms, tensor 81.1%, regs 128,
// 2 CTAs/SM). Five restructuring attempts regressed; R8 is the local optimum.
//
// R10 change: prep only. Dequant writes were 50%-sector-efficient scattered
// 16B stores (consecutive threads 8KB apart). Now: smem tile transpose —
// block owns 16n x 512r, reads qweight coalesced, one warp per n writes
// perfectly contiguous 512B bursts along K. Same float math (rel_err must
// stay bit-identical at 2.934e-4).
// ============================================================================

constexpr int M = 8192;
constexpr int N = 11008;
constexpr int K = 4096;

constexpr int BM = 128;
constexpr int BN = 128;
constexpr int KC = 64;             // halves per stage = 128B rows (SW128)
constexpr int STAGES = 3;
constexpr int NK = K / KC;         // 64
constexpr int THREADS = 256;

constexpr int A_BYTES = BM * 128;                 // 16384
constexpr int STAGE_BYTES = 2 * A_BYTES;          // 32768 (A then B)
constexpr int SMEM_BYTES = STAGES * STAGE_BYTES;  // 98304 -> 2 CTAs/SM

constexpr int KR = K / 8;               // 512 qweight rows
constexpr int XWORK   = M * K / 4;      // float4 items in convert part
constexpr int XBLOCKS = XWORK / 256;    // 32768 (exact)
constexpr int WBLOCKS = N / 16;         // 688 transpose-dequant blocks

static_assert(M % BM == 0 && N % BN == 0 && K % KC == 0, "exact tiling");

__device__ __half g_X[(size_t)M * K];   // [M, K] fp16
__device__ __half g_W[(size_t)N * K];   // [N, K] fp16 (W^T), K-major

// ----------------------------------------------------------------------------
// helpers
// ----------------------------------------------------------------------------
__device__ __forceinline__ void cp16(uint32_t smem_dst, const void* gsrc) {
    asm volatile("cp.async.cg.shared.global [%0], [%1], 16;"
                 :: "r"(smem_dst), "l"(gsrc));
}

__device__ __forceinline__ void ldsm4(uint32_t* r, uint32_t addr) {
    asm volatile("ldmatrix.sync.aligned.m8n8.x4.shared.b16 {%0,%1,%2,%3}, [%4];"
                 : "=r"(r[0]), "=r"(r[1]), "=r"(r[2]), "=r"(r[3]) : "r"(addr));
}

__device__ __forceinline__ void mma16816(float* c, const uint32_t* a, const uint32_t* b) {
    asm volatile(
        "mma.sync.aligned.m16n8k16.row.col.f32.f16.f16.f32 "
        "{%0,%1,%2,%3}, {%4,%5,%6,%7}, {%8,%9}, {%0,%1,%2,%3};"
        : "+f"(c[0]), "+f"(c[1]), "+f"(c[2]), "+f"(c[3])
        : "r"(a[0]), "r"(a[1]), "r"(a[2]), "r"(a[3]), "r"(b[0]), "r"(b[1]));
}

// ----------------------------------------------------------------------------
// Pass 1: fused prep.
//  blocks [0, XBLOCKS):          x fp32 -> fp16 (unchanged, coalesced)
//  blocks [XBLOCKS, +WBLOCKS):   dequant 16 n x 512 r via smem transpose
// ----------------------------------------------------------------------------
__global__ void __launch_bounds__(256)
prep_kernel(const float* __restrict__ x, const int* __restrict__ qweight,
            const float* __restrict__ scales, const int* __restrict__ qzeros) {
    __shared__ unsigned sw[KR * 17];                 // 512 x 16, pad 17
    const int t = threadIdx.x;
    const int bid = blockIdx.x;

    if (bid < XBLOCKS) {
        int idx = bid * 256 + t;                     // over M*K/4 (exact)
        float4 v = ((const float4*)x)[idx];
        __half2 h0 = __floats2half2_rn(v.x, v.y);
        __half2 h1 = __floats2half2_rn(v.z, v.w);
        uint2 o;
        o.x = *(unsigned*)&h0;
        o.y = *(unsigned*)&h1;
        ((uint2*)g_X)[idx] = o;
        return;
    }

    const int n0 = (bid - XBLOCKS) * 16;
    const unsigned* qw = (const unsigned*)qweight;

    // phase 1: coalesced load of qweight tile [512 r x 16 n]
#pragma unroll
    for (int w = 0; w < 32; w++) {
        int idx = w * 256 + t;                       // 0..8191
        int r  = idx >> 4;
        int nl = idx & 15;
        sw[r * 17 + nl] = qw[(size_t)r * N + n0 + nl];
    }
    __syncthreads();

    // phase 2: warp per n; lanes sweep consecutive r -> 512B contiguous stores
    const int wid  = t >> 5;
    const int lane = t & 31;
#pragma unroll
    for (int pass = 0; pass < 2; pass++) {
        const int nl = wid + pass * 8;               // 0..15
        const int n  = n0 + nl;
#pragma unroll
        for (int rb = 0; rb < KR; rb += 32) {
            const int r = rb + lane;
            const int g = r >> 4;                    // groupsize 128 = 16 rows
            unsigned q  = sw[r * 17 + nl];
            unsigned qz = ((const unsigned*)qzeros)[(size_t)g * (N / 8) + (n >> 3)];
            float z = (float)((qz >> ((n & 7) * 4)) & 0xF);
            float s = scales[(size_t)g * N + n];
            __half2 outv[4];
#pragma unroll
            for (int j = 0; j < 4; j++) {
                float v0 = s * ((float)((q >> (8 * j))     & 0xF) - z);
                float v1 = s * ((float)((q >> (8 * j + 4)) & 0xF) - z);
                outv[j] = __floats2half2_rn(v0, v1);
            }
            *(uint4*)&g_W[(size_t)n * K + r * 8] = *(uint4*)outv;
        }
    }
}

// ----------------------------------------------------------------------------
// Stage loader (verbatim R8): A 128 rows + B 128 rows, 128B/row, SW128.
// Row r, 16B chunk c at r*128 + ((c ^ (r&7))*16).
// ----------------------------------------------------------------------------
__device__ __forceinline__ void load_stage(uint32_t sbase, int slot, int kt,
                                           const __half* Ag, const __half* Bg,
                                           int tid) {
    const uint32_t a_s = sbase + slot * STAGE_BYTES;
    const uint32_t b_s = a_s + A_BYTES;
    const __half* Ak = Ag + kt * KC;
    const __half* Bk = Bg + kt * KC;
#pragma unroll
    for (int it = 0; it < 4; it++) {        // 128 rows * 8 chunks / 256 thr
        int idx = tid + it * THREADS;
        int r = idx >> 3, c = idx & 7;
        uint32_t off = (uint32_t)r * 128 + (uint32_t)((c ^ (r & 7)) * 16);
        cp16(a_s + off, Ak + (size_t)r * K + c * 8);
        cp16(b_s + off, Bk + (size_t)r * K + c * 8);
    }
}

// ----------------------------------------------------------------------------
// Pass 2: GEMM (verbatim R8 — best measured; do not touch)
// ----------------------------------------------------------------------------
__global__ void __launch_bounds__(THREADS, 2)
gemm_kernel(float* __restrict__ out) {
    extern __shared__ char smem[];
    const uint32_t sbase = (uint32_t)__cvta_generic_to_shared(smem);
    const int tid  = threadIdx.x;
    const int warp = tid >> 5;
    const int lane = tid & 31;
    const int wm = warp & 1;          // 2 warps over 128 M (64 each)
    const int wn = warp >> 1;         // 4 warps over 128 N (32 each)
    const int m0 = blockIdx.x * BM;
    const int n0 = blockIdx.y * BN;

    const __half* Ag = g_X + (size_t)m0 * K;
    const __half* Bg = g_W + (size_t)n0 * K;

    float acc[4][4][4];
#pragma unroll
    for (int i = 0; i < 4; i++)
#pragma unroll
        for (int j = 0; j < 4; j++)
#pragma unroll
            for (int e = 0; e < 4; e++) acc[i][j][e] = 0.f;

    // ldmatrix address components (validated R2..R9):
    const int arow = wm * 64 + (lane & 15);
    const int asel = lane >> 4;                              // k-chunk +0/+1
    const int brow = wn * 32 + (((lane >> 4) & 1) << 3) + (lane & 7);
    const int bsel = (lane >> 3) & 1;

    // prologue: fills for stages 0,1 in flight; stage 0 resident after sync
    load_stage(sbase, 0, 0, Ag, Bg, tid);
    asm volatile("cp.async.commit_group;" ::: "memory");
    load_stage(sbase, 1, 1, Ag, Bg, tid);
    asm volatile("cp.async.commit_group;" ::: "memory");
    asm volatile("cp.async.wait_group 1;" ::: "memory");
    __syncthreads();

    int slot = 0;
    for (int i = 0; i < NK; i++) {
        // stage i resident: compute first (no LDGSTS in front of first MMA)
        const uint32_t a_s = sbase + slot * STAGE_BYTES;
        const uint32_t b_s = a_s + A_BYTES;
#pragma unroll
        for (int ks = 0; ks < KC / 16; ks++) {
            uint32_t a[4][4], b[2][4];
#pragma unroll
            for (int mf = 0; mf < 4; mf++) {
                int row = arow + mf * 16;
                int kc  = ks * 2 + asel;
                ldsm4(a[mf], a_s + row * 128 + ((kc ^ (row & 7)) * 16));
            }
#pragma unroll
            for (int nf2 = 0; nf2 < 2; nf2++) {
                int row = brow + nf2 * 16;
                int kc  = ks * 2 + bsel;
                ldsm4(b[nf2], b_s + row * 128 + ((kc ^ (row & 7)) * 16));
            }
#pragma unroll
            for (int mf = 0; mf < 4; mf++)
#pragma unroll
                for (int nf = 0; nf < 4; nf++)
                    mma16816(acc[mf][nf], a[mf], &b[nf >> 1][(nf & 1) * 2]);
        }

        // issue fill for stage i+2 into slot (i+2)%3 = slot(i-1): all reads of
        // that slot finished before the barrier at the end of iter i-1.
        if (i + 2 < NK) {
            int ns = slot - 1; if (ns < 0) ns += STAGES;     // (i+2) % 3
            load_stage(sbase, ns, i + 2, Ag, Bg, tid);
        }
        asm volatile("cp.async.commit_group;" ::: "memory");

        slot++; if (slot == STAGES) slot = 0;

        // advance: <=1 group pending (the fill just issued) => stage i+1 landed
        if (i + 1 < NK) {
            asm volatile("cp.async.wait_group 1;" ::: "memory");
            __syncthreads();
        }
    }

    // Epilogue (verbatim R8): register -> gmem float2 stores
    const int mbase = m0 + wm * 64 + (lane >> 2);
    const int nbase = n0 + wn * 32 + (lane & 3) * 2;
#pragma unroll
    for (int mf = 0; mf < 4; mf++)
#pragma unroll
        for (int nf = 0; nf < 4; nf++) {
            float* p0 = &out[(size_t)(mbase + mf * 16)     * N + nbase + nf * 8];
            float* p1 = &out[(size_t)(mbase + mf * 16 + 8) * N + nbase + nf * 8];
            *(float2*)p0 = make_float2(acc[mf][nf][0], acc[mf][nf][1]);
            *(float2*)p1 = make_float2(acc[mf][nf][2], acc[mf][nf][3]);
        }
}

// ----------------------------------------------------------------------------
extern "C" void kernel_launch(void* const* d_in, const int* in_sizes, int n_in,
                              void* d_out, int out_size) {
    (void)in_sizes; (void)n_in; (void)out_size;
    const float* x       = (const float*)d_in[0];
    const int*   qweight = (const int*)d_in[1];
    const float* scales  = (const float*)d_in[2];
    const int*   qzeros  = (const int*)d_in[3];
    float* out = (float*)d_out;

    prep_kernel<<<XBLOCKS + WBLOCKS, 256>>>(x, qweight, scales, qzeros);

    cudaFuncSetAttribute(gemm_kernel, cudaFuncAttributeMaxDynamicSharedMemorySize,
                         SMEM_BYTES);
    dim3 grid(M / BM, N / BN);   // (64, 86), m-fast: wave shares B via L2
    gemm_kernel<<<grid, THREADS, SMEM_BYTES>>>(out);
}

// round 11
// speedup vs baseline: 1.0412x; 1.0007x over previous
#include <cuda_runtime.h>
#include <cuda_fp16.h>
#include <cstdint>

// ============================================================================
// QuantLinear: out[M,N] = x[M,K] @ dequant(qweight, scales, qzeros)[K,N]
// M=8192, K=4096, N=11008, groupsize=128, 4-bit.
//
// compute_103 => mma.sync HMMA, rt_SMSP=8; GEMM floor 1.21ms.
// GEMM mainloop = R8 (best measured: 1.503ms, tensor 80.9%, 2 CTAs/SM).
// Crossbar and tensor demand are exactly co-saturated (2048 cyc each per
// stage-pair) — mainloop is at its local optimum; frozen.
//
// R11 (banking round): epilogue stores use st.global.cs (streaming, protect
// the 64MB A working set in L2); prep phase-1 qweight loads vectorized uint4.
// ============================================================================

constexpr int M = 8192;
constexpr int N = 11008;
constexpr int K = 4096;

constexpr int BM = 128;
constexpr int BN = 128;
constexpr int KC = 64;             // halves per stage = 128B rows (SW128)
constexpr int STAGES = 3;
constexpr int NK = K / KC;         // 64
constexpr int THREADS = 256;

constexpr int A_BYTES = BM * 128;                 // 16384
constexpr int STAGE_BYTES = 2 * A_BYTES;          // 32768 (A then B)
constexpr int SMEM_BYTES = STAGES * STAGE_BYTES;  // 98304 -> 2 CTAs/SM

constexpr int KR = K / 8;               // 512 qweight rows
constexpr int XWORK   = M * K / 4;      // float4 items in convert part
constexpr int XBLOCKS = XWORK / 256;    // 32768 (exact)
constexpr int WBLOCKS = N / 16;         // 688 transpose-dequant blocks

static_assert(M % BM == 0 && N % BN == 0 && K % KC == 0, "exact tiling");

__device__ __half g_X[(size_t)M * K];   // [M, K] fp16
__device__ __half g_W[(size_t)N * K];   // [N, K] fp16 (W^T), K-major

// ----------------------------------------------------------------------------
// helpers
// ----------------------------------------------------------------------------
__device__ __forceinline__ void cp16(uint32_t smem_dst, const void* gsrc) {
    asm volatile("cp.async.cg.shared.global [%0], [%1], 16;"
                 :: "r"(smem_dst), "l"(gsrc));
}

__device__ __forceinline__ void ldsm4(uint32_t* r, uint32_t addr) {
    asm volatile("ldmatrix.sync.aligned.m8n8.x4.shared.b16 {%0,%1,%2,%3}, [%4];"
                 : "=r"(r[0]), "=r"(r[1]), "=r"(r[2]), "=r"(r[3]) : "r"(addr));
}

__device__ __forceinline__ void mma16816(float* c, const uint32_t* a, const uint32_t* b) {
    asm volatile(
        "mma.sync.aligned.m16n8k16.row.col.f32.f16.f16.f32 "
        "{%0,%1,%2,%3}, {%4,%5,%6,%7}, {%8,%9}, {%0,%1,%2,%3};"
        : "+f"(c[0]), "+f"(c[1]), "+f"(c[2]), "+f"(c[3])
        : "r"(a[0]), "r"(a[1]), "r"(a[2]), "r"(a[3]), "r"(b[0]), "r"(b[1]));
}

__device__ __forceinline__ void stcs2(float* p, float a, float b) {
    asm volatile("st.global.cs.v2.f32 [%0], {%1, %2};"
                 :: "l"(p), "f"(a), "f"(b) : "memory");
}

// ----------------------------------------------------------------------------
// Pass 1: fused prep.
//  blocks [0, XBLOCKS):          x fp32 -> fp16 (coalesced)
//  blocks [XBLOCKS, +WBLOCKS):   dequant 16 n x 512 r via smem transpose
// ----------------------------------------------------------------------------
__global__ void __launch_bounds__(256)
prep_kernel(const float* __restrict__ x, const int* __restrict__ qweight,
            const float* __restrict__ scales, const int* __restrict__ qzeros) {
    __shared__ unsigned sw[KR * 17];                 // 512 x 16, pad 17
    const int t = threadIdx.x;
    const int bid = blockIdx.x;

    if (bid < XBLOCKS) {
        int idx = bid * 256 + t;                     // over M*K/4 (exact)
        float4 v = ((const float4*)x)[idx];
        __half2 h0 = __floats2half2_rn(v.x, v.y);
        __half2 h1 = __floats2half2_rn(v.z, v.w);
        uint2 o;
        o.x = *(unsigned*)&h0;
        o.y = *(unsigned*)&h1;
        ((uint2*)g_X)[idx] = o;
        return;
    }

    const int n0 = (bid - XBLOCKS) * 16;
    const unsigned* qw = (const unsigned*)qweight;

    // phase 1: qweight tile [512 r x 16 n], uint4 per thread (4 n-words)
#pragma unroll
    for (int w = 0; w < 8; w++) {
        int idx = w * 256 + t;                       // 0..2047 quads
        int r  = idx >> 2;
        int q4 = idx & 3;
        uint4 v = *(const uint4*)&qw[(size_t)r * N + n0 + q4 * 4];
        sw[r * 17 + q4 * 4 + 0] = v.x;
        sw[r * 17 + q4 * 4 + 1] = v.y;
        sw[r * 17 + q4 * 4 + 2] = v.z;
        sw[r * 17 + q4 * 4 + 3] = v.w;
    }
    __syncthreads();

    // phase 2: warp per n; lanes sweep consecutive r -> 512B contiguous stores
    const int wid  = t >> 5;
    const int lane = t & 31;
#pragma unroll
    for (int pass = 0; pass < 2; pass++) {
        const int nl = wid + pass * 8;               // 0..15
        const int n  = n0 + nl;
#pragma unroll
        for (int rb = 0; rb < KR; rb += 32) {
            const int r = rb + lane;
            const int g = r >> 4;                    // groupsize 128 = 16 rows
            unsigned q  = sw[r * 17 + nl];
            unsigned qz = ((const unsigned*)qzeros)[(size_t)g * (N / 8) + (n >> 3)];
            float z = (float)((qz >> ((n & 7) * 4)) & 0xF);
            float s = scales[(size_t)g * N + n];
            __half2 outv[4];
#pragma unroll
            for (int j = 0; j < 4; j++) {
                float v0 = s * ((float)((q >> (8 * j))     & 0xF) - z);
                float v1 = s * ((float)((q >> (8 * j + 4)) & 0xF) - z);
                outv[j] = __floats2half2_rn(v0, v1);
            }
            *(uint4*)&g_W[(size_t)n * K + r * 8] = *(uint4*)outv;
        }
    }
}

// ----------------------------------------------------------------------------
// Stage loader (verbatim R8): A 128 rows + B 128 rows, 128B/row, SW128.
// Row r, 16B chunk c at r*128 + ((c ^ (r&7))*16).
// ----------------------------------------------------------------------------
__device__ __forceinline__ void load_stage(uint32_t sbase, int slot, int kt,
                                           const __half* Ag, const __half* Bg,
                                           int tid) {
    const uint32_t a_s = sbase + slot * STAGE_BYTES;
    const uint32_t b_s = a_s + A_BYTES;
    const __half* Ak = Ag + kt * KC;
    const __half* Bk = Bg + kt * KC;
#pragma unroll
    for (int it = 0; it < 4; it++) {        // 128 rows * 8 chunks / 256 thr
        int idx = tid + it * THREADS;
        int r = idx >> 3, c = idx & 7;
        uint32_t off = (uint32_t)r * 128 + (uint32_t)((c ^ (r & 7)) * 16);
        cp16(a_s + off, Ak + (size_t)r * K + c * 8);
        cp16(b_s + off, Bk + (size_t)r * K + c * 8);
    }
}

// ----------------------------------------------------------------------------
// Pass 2: GEMM (mainloop verbatim R8 — frozen)
// ----------------------------------------------------------------------------
__global__ void __launch_bounds__(THREADS, 2)
gemm_kernel(float* __restrict__ out) {
    extern __shared__ char smem[];
    const uint32_t sbase = (uint32_t)__cvta_generic_to_shared(smem);
    const int tid  = threadIdx.x;
    const int warp = tid >> 5;
    const int lane = tid & 31;
    const int wm = warp & 1;          // 2 warps over 128 M (64 each)
    const int wn = warp >> 1;         // 4 warps over 128 N (32 each)
    const int m0 = blockIdx.x * BM;
    const int n0 = blockIdx.y * BN;

    const __half* Ag = g_X + (size_t)m0 * K;
    const __half* Bg = g_W + (size_t)n0 * K;

    float acc[4][4][4];
#pragma unroll
    for (int i = 0; i < 4; i++)
#pragma unroll
        for (int j = 0; j < 4; j++)
#pragma unroll
            for (int e = 0; e < 4; e++) acc[i][j][e] = 0.f;

    // ldmatrix address components (validated R2..R10):
    const int arow = wm * 64 + (lane & 15);
    const int asel = lane >> 4;                              // k-chunk +0/+1
    const int brow = wn * 32 + (((lane >> 4) & 1) << 3) + (lane & 7);
    const int bsel = (lane >> 3) & 1;

    // prologue: fills for stages 0,1 in flight; stage 0 resident after sync
    load_stage(sbase, 0, 0, Ag, Bg, tid);
    asm volatile("cp.async.commit_group;" ::: "memory");
    load_stage(sbase, 1, 1, Ag, Bg, tid);
    asm volatile("cp.async.commit_group;" ::: "memory");
    asm volatile("cp.async.wait_group 1;" ::: "memory");
    __syncthreads();

    int slot = 0;
    for (int i = 0; i < NK; i++) {
        // stage i resident: compute first (no LDGSTS in front of first MMA)
        const uint32_t a_s = sbase + slot * STAGE_BYTES;
        const uint32_t b_s = a_s + A_BYTES;
#pragma unroll
        for (int ks = 0; ks < KC / 16; ks++) {
            uint32_t a[4][4], b[2][4];
#pragma unroll
            for (int mf = 0; mf < 4; mf++) {
                int row = arow + mf * 16;
                int kc  = ks * 2 + asel;
                ldsm4(a[mf], a_s + row * 128 + ((kc ^ (row & 7)) * 16));
            }
#pragma unroll
            for (int nf2 = 0; nf2 < 2; nf2++) {
                int row = brow + nf2 * 16;
                int kc  = ks * 2 + bsel;
                ldsm4(b[nf2], b_s + row * 128 + ((kc ^ (row & 7)) * 16));
            }
#pragma unroll
            for (int mf = 0; mf < 4; mf++)
#pragma unroll
                for (int nf = 0; nf < 4; nf++)
                    mma16816(acc[mf][nf], a[mf], &b[nf >> 1][(nf & 1) * 2]);
        }

        // issue fill for stage i+2 into slot (i+2)%3 = slot(i-1): all reads of
        // that slot finished before the barrier at the end of iter i-1.
        if (i + 2 < NK) {
            int ns = slot - 1; if (ns < 0) ns += STAGES;     // (i+2) % 3
            load_stage(sbase, ns, i + 2, Ag, Bg, tid);
        }
        asm volatile("cp.async.commit_group;" ::: "memory");

        slot++; if (slot == STAGES) slot = 0;

        // advance: <=1 group pending (the fill just issued) => stage i+1 landed
        if (i + 1 < NK) {
            asm volatile("cp.async.wait_group 1;" ::: "memory");
            __syncthreads();
        }
    }

    // Epilogue: streaming stores (output is write-once; keep A resident in L2)
    const int mbase = m0 + wm * 64 + (lane >> 2);
    const int nbase = n0 + wn * 32 + (lane & 3) * 2;
#pragma unroll
    for (int mf = 0; mf < 4; mf++)
#pragma unroll
        for (int nf = 0; nf < 4; nf++) {
            float* p0 = &out[(size_t)(mbase + mf * 16)     * N + nbase + nf * 8];
            float* p1 = &out[(size_t)(mbase + mf * 16 + 8) * N + nbase + nf * 8];
            stcs2(p0, acc[mf][nf][0], acc[mf][nf][1]);
            stcs2(p1, acc[mf][nf][2], acc[mf][nf][3]);
        }
}

// ----------------------------------------------------------------------------
extern "C" void kernel_launch(void* const* d_in, const int* in_sizes, int n_in,
                              void* d_out, int out_size) {
    (void)in_sizes; (void)n_in; (void)out_size;
    const float* x       = (const float*)d_in[0];
    const int*   qweight = (const int*)d_in[1];
    const float* scales  = (const float*)d_in[2];
    const int*   qzeros  = (const int*)d_in[3];
    float* out = (float*)d_out;

    prep_kernel<<<XBLOCKS + WBLOCKS, 256>>>(x, qweight, scales, qzeros);

    cudaFuncSetAttribute(gemm_kernel, cudaFuncAttributeMaxDynamicSharedMemorySize,
                         SMEM_BYTES);
    dim3 grid(M / BM, N / BN);   // (64, 86), m-fast: wave shares B via L2
    gemm_kernel<<<grid, THREADS, SMEM_BYTES>>>(out);
}

// round 12
// speedup vs baseline: 1.0425x; 1.0012x over previous
#include <cuda_runtime.h>
#include <cuda_fp16.h>
#include <cstdint>

// ============================================================================
// QuantLinear: out[M,N] = x[M,K] @ dequant(qweight, scales, qzeros)[K,N]
// M=8192, K=4096, N=11008, groupsize=128, 4-bit.
//
// compute_103 => mma.sync HMMA, rt_SMSP=8; GEMM floor 1.21ms.
// GEMM mainloop = R8 (best measured: 1.503ms, tensor 80.9%, 2 CTAs/SM).
// Crossbar and tensor demand are exactly co-saturated (2048 cyc each per
// stage-pair) — mainloop is at its local optimum; frozen.
//
// R11 (banking round): epilogue stores use st.global.cs (streaming, protect
// the 64MB A working set in L2); prep phase-1 qweight loads vectorized uint4.
// ============================================================================

constexpr int M = 8192;
constexpr int N = 11008;
constexpr int K = 4096;

constexpr int BM = 128;
constexpr int BN = 128;
constexpr int KC = 64;             // halves per stage = 128B rows (SW128)
constexpr int STAGES = 3;
constexpr int NK = K / KC;         // 64
constexpr int THREADS = 256;

constexpr int A_BYTES = BM * 128;                 // 16384
constexpr int STAGE_BYTES = 2 * A_BYTES;          // 32768 (A then B)
constexpr int SMEM_BYTES = STAGES * STAGE_BYTES;  // 98304 -> 2 CTAs/SM

constexpr int KR = K / 8;               // 512 qweight rows
constexpr int XWORK   = M * K / 4;      // float4 items in convert part
constexpr int XBLOCKS = XWORK / 256;    // 32768 (exact)
constexpr int WBLOCKS = N / 16;         // 688 transpose-dequant blocks

static_assert(M % BM == 0 && N % BN == 0 && K % KC == 0, "exact tiling");

__device__ __half g_X[(size_t)M * K];   // [M, K] fp16
__device__ __half g_W[(size_t)N * K];   // [N, K] fp16 (W^T), K-major

// ----------------------------------------------------------------------------
// helpers
// ----------------------------------------------------------------------------
__device__ __forceinline__ void cp16(uint32_t smem_dst, const void* gsrc) {
    asm volatile("cp.async.cg.shared.global [%0], [%1], 16;"
                 :: "r"(smem_dst), "l"(gsrc));
}

__device__ __forceinline__ void ldsm4(uint32_t* r, uint32_t addr) {
    asm volatile("ldmatrix.sync.aligned.m8n8.x4.shared.b16 {%0,%1,%2,%3}, [%4];"
                 : "=r"(r[0]), "=r"(r[1]), "=r"(r[2]), "=r"(r[3]) : "r"(addr));
}

__device__ __forceinline__ void mma16816(float* c, const uint32_t* a, const uint32_t* b) {
    asm volatile(
        "mma.sync.aligned.m16n8k16.row.col.f32.f16.f16.f32 "
        "{%0,%1,%2,%3}, {%4,%5,%6,%7}, {%8,%9}, {%0,%1,%2,%3};"
        : "+f"(c[0]), "+f"(c[1]), "+f"(c[2]), "+f"(c[3])
        : "r"(a[0]), "r"(a[1]), "r"(a[2]), "r"(a[3]), "r"(b[0]), "r"(b[1]));
}

__device__ __forceinline__ void stcs2(float* p, float a, float b) {
    asm volatile("st.global.cs.v2.f32 [%0], {%1, %2};"
                 :: "l"(p), "f"(a), "f"(b) : "memory");
}

// ----------------------------------------------------------------------------
// Pass 1: fused prep.
//  blocks [0, XBLOCKS):          x fp32 -> fp16 (coalesced)
//  blocks [XBLOCKS, +WBLOCKS):   dequant 16 n x 512 r via smem transpose
// ----------------------------------------------------------------------------
__global__ void __launch_bounds__(256)
prep_kernel(const float* __restrict__ x, const int* __restrict__ qweight,
            const float* __restrict__ scales, const int* __restrict__ qzeros) {
    __shared__ unsigned sw[KR * 17];                 // 512 x 16, pad 17
    const int t = threadIdx.x;
    const int bid = blockIdx.x;

    if (bid < XBLOCKS) {
        int idx = bid * 256 + t;                     // over M*K/4 (exact)
        float4 v = ((const float4*)x)[idx];
        __half2 h0 = __floats2half2_rn(v.x, v.y);
        __half2 h1 = __floats2half2_rn(v.z, v.w);
        uint2 o;
        o.x = *(unsigned*)&h0;
        o.y = *(unsigned*)&h1;
        ((uint2*)g_X)[idx] = o;
        return;
    }

    const int n0 = (bid - XBLOCKS) * 16;
    const unsigned* qw = (const unsigned*)qweight;

    // phase 1: qweight tile [512 r x 16 n], uint4 per thread (4 n-words)
#pragma unroll
    for (int w = 0; w < 8; w++) {
        int idx = w * 256 + t;                       // 0..2047 quads
        int r  = idx >> 2;
        int q4 = idx & 3;
        uint4 v = *(const uint4*)&qw[(size_t)r * N + n0 + q4 * 4];
        sw[r * 17 + q4 * 4 + 0] = v.x;
        sw[r * 17 + q4 * 4 + 1] = v.y;
        sw[r * 17 + q4 * 4 + 2] = v.z;
        sw[r * 17 + q4 * 4 + 3] = v.w;
    }
    __syncthreads();

    // phase 2: warp per n; lanes sweep consecutive r -> 512B contiguous stores
    const int wid  = t >> 5;
    const int lane = t & 31;
#pragma unroll
    for (int pass = 0; pass < 2; pass++) {
        const int nl = wid + pass * 8;               // 0..15
        const int n  = n0 + nl;
#pragma unroll
        for (int rb = 0; rb < KR; rb += 32) {
            const int r = rb + lane;
            const int g = r >> 4;                    // groupsize 128 = 16 rows
            unsigned q  = sw[r * 17 + nl];
            unsigned qz = ((const unsigned*)qzeros)[(size_t)g * (N / 8) + (n >> 3)];
            float z = (float)((qz >> ((n & 7) * 4)) & 0xF);
            float s = scales[(size_t)g * N + n];
            __half2 outv[4];
#pragma unroll
            for (int j = 0; j < 4; j++) {
                float v0 = s * ((float)((q >> (8 * j))     & 0xF) - z);
                float v1 = s * ((float)((q >> (8 * j + 4)) & 0xF) - z);
                outv[j] = __floats2half2_rn(v0, v1);
            }
            *(uint4*)&g_W[(size_t)n * K + r * 8] = *(uint4*)outv;
        }
    }
}

// ----------------------------------------------------------------------------
// Stage loader (verbatim R8): A 128 rows + B 128 rows, 128B/row, SW128.
// Row r, 16B chunk c at r*128 + ((c ^ (r&7))*16).
// ----------------------------------------------------------------------------
__device__ __forceinline__ void load_stage(uint32_t sbase, int slot, int kt,
                                           const __half* Ag, const __half* Bg,
                                           int tid) {
    const uint32_t a_s = sbase + slot * STAGE_BYTES;
    const uint32_t b_s = a_s + A_BYTES;
    const __half* Ak = Ag + kt * KC;
    const __half* Bk = Bg + kt * KC;
#pragma unroll
    for (int it = 0; it < 4; it++) {        // 128 rows * 8 chunks / 256 thr
        int idx = tid + it * THREADS;
        int r = idx >> 3, c = idx & 7;
        uint32_t off = (uint32_t)r * 128 + (uint32_t)((c ^ (r & 7)) * 16);
        cp16(a_s + off, Ak + (size_t)r * K + c * 8);
        cp16(b_s + off, Bk + (size_t)r * K + c * 8);
    }
}

// ----------------------------------------------------------------------------
// Pass 2: GEMM (mainloop verbatim R8 — frozen)
// ----------------------------------------------------------------------------
__global__ void __launch_bounds__(THREADS, 2)
gemm_kernel(float* __restrict__ out) {
    extern __shared__ char smem[];
    const uint32_t sbase = (uint32_t)__cvta_generic_to_shared(smem);
    const int tid  = threadIdx.x;
    const int warp = tid >> 5;
    const int lane = tid & 31;
    const int wm = warp & 1;          // 2 warps over 128 M (64 each)
    const int wn = warp >> 1;         // 4 warps over 128 N (32 each)
    const int m0 = blockIdx.x * BM;
    const int n0 = blockIdx.y * BN;

    const __half* Ag = g_X + (size_t)m0 * K;
    const __half* Bg = g_W + (size_t)n0 * K;

    float acc[4][4][4];
#pragma unroll
    for (int i = 0; i < 4; i++)
#pragma unroll
        for (int j = 0; j < 4; j++)
#pragma unroll
            for (int e = 0; e < 4; e++) acc[i][j][e] = 0.f;

    // ldmatrix address components (validated R2..R10):
    const int arow = wm * 64 + (lane & 15);
    const int asel = lane >> 4;                              // k-chunk +0/+1
    const int brow = wn * 32 + (((lane >> 4) & 1) << 3) + (lane & 7);
    const int bsel = (lane >> 3) & 1;

    // prologue: fills for stages 0,1 in flight; stage 0 resident after sync
    load_stage(sbase, 0, 0, Ag, Bg, tid);
    asm volatile("cp.async.commit_group;" ::: "memory");
    load_stage(sbase, 1, 1, Ag, Bg, tid);
    asm volatile("cp.async.commit_group;" ::: "memory");
    asm volatile("cp.async.wait_group 1;" ::: "memory");
    __syncthreads();

    int slot = 0;
    for (int i = 0; i < NK; i++) {
        // stage i resident: compute first (no LDGSTS in front of first MMA)
        const uint32_t a_s = sbase + slot * STAGE_BYTES;
        const uint32_t b_s = a_s + A_BYTES;
#pragma unroll
        for (int ks = 0; ks < KC / 16; ks++) {
            uint32_t a[4][4], b[2][4];
#pragma unroll
            for (int mf = 0; mf < 4; mf++) {
                int row = arow + mf * 16;
                int kc  = ks * 2 + asel;
                ldsm4(a[mf], a_s + row * 128 + ((kc ^ (row & 7)) * 16));
            }
#pragma unroll
            for (int nf2 = 0; nf2 < 2; nf2++) {
                int row = brow + nf2 * 16;
                int kc  = ks * 2 + bsel;
                ldsm4(b[nf2], b_s + row * 128 + ((kc ^ (row & 7)) * 16));
            }
#pragma unroll
            for (int mf = 0; mf < 4; mf++)
#pragma unroll
                for (int nf = 0; nf < 4; nf++)
                    mma16816(acc[mf][nf], a[mf], &b[nf >> 1][(nf & 1) * 2]);
        }

        // issue fill for stage i+2 into slot (i+2)%3 = slot(i-1): all reads of
        // that slot finished before the barrier at the end of iter i-1.
        if (i + 2 < NK) {
            int ns = slot - 1; if (ns < 0) ns += STAGES;     // (i+2) % 3
            load_stage(sbase, ns, i + 2, Ag, Bg, tid);
        }
        asm volatile("cp.async.commit_group;" ::: "memory");

        slot++; if (slot == STAGES) slot = 0;

        // advance: <=1 group pending (the fill just issued) => stage i+1 landed
        if (i + 1 < NK) {
            asm volatile("cp.async.wait_group 1;" ::: "memory");
            __syncthreads();
        }
    }

    // Epilogue: streaming stores (output is write-once; keep A resident in L2)
    const int mbase = m0 + wm * 64 + (lane >> 2);
    const int nbase = n0 + wn * 32 + (lane & 3) * 2;
#pragma unroll
    for (int mf = 0; mf < 4; mf++)
#pragma unroll
        for (int nf = 0; nf < 4; nf++) {
            float* p0 = &out[(size_t)(mbase + mf * 16)     * N + nbase + nf * 8];
            float* p1 = &out[(size_t)(mbase + mf * 16 + 8) * N + nbase + nf * 8];
            stcs2(p0, acc[mf][nf][0], acc[mf][nf][1]);
            stcs2(p1, acc[mf][nf][2], acc[mf][nf][3]);
        }
}

// ----------------------------------------------------------------------------
extern "C" void kernel_launch(void* const* d_in, const int* in_sizes, int n_in,
                              void* d_out, int out_size) {
    (void)in_sizes; (void)n_in; (void)out_size;
    const float* x       = (const float*)d_in[0];
    const int*   qweight = (const int*)d_in[1];
    const float* scales  = (const float*)d_in[2];
    const int*   qzeros  = (const int*)d_in[3];
    float* out = (float*)d_out;

    prep_kernel<<<XBLOCKS + WBLOCKS, 256>>>(x, qweight, scales, qzeros);

    cudaFuncSetAttribute(gemm_kernel, cudaFuncAttributeMaxDynamicSharedMemorySize,
                         SMEM_BYTES);
    dim3 grid(M / BM, N / BN);   // (64, 86), m-fast: wave shares B via L2
    gemm_kernel<<<grid, THREADS, SMEM_BYTES>>>(out);
}